// round 12
// baseline (speedup 1.0000x reference)
#include <cuda_runtime.h>
#include <math.h>

#define H       2048
#define E       8
#define HV      (H / 4)        // 512 16B-chunks per row
#define WSTR    513            // padded weight row stride in 16B units
#define TPW     8              // tokens per warp
#define NWARPS  8
#define TPB     (TPW * NWARPS) // 64 tokens per block
#define NTHR    256
#define NIT     32             // 16 h-chunks per iter
#define ALPHA   0.01f

__device__ float        g_acc[2 * E];   // [0..7] counts, [8..15] prob sums
__device__ unsigned int g_done = 0;

__device__ __forceinline__ void ffma2(unsigned long long& d,
                                      unsigned long long a,
                                      unsigned long long b)
{
    asm("fma.rn.f32x2 %0, %1, %2, %0;" : "+l"(d) : "l"(a), "l"(b));
}

__device__ __forceinline__ float pair_sum(unsigned long long p)
{
    float lo, hi;
    asm("mov.b64 {%0, %1}, %2;" : "=f"(lo), "=f"(hi) : "l"(p));
    return lo + hi;
}

__global__ __launch_bounds__(NTHR, 2)
void moe_gate_kernel(const float* __restrict__ x,
                     const float* __restrict__ w,
                     float* __restrict__ out_idx,
                     float* __restrict__ out_wgt,
                     float* __restrict__ out_aux,
                     int T)
{
    extern __shared__ char smem[];               // padded weights: 8*513*16B
    ulonglong2* w8s = reinterpret_cast<ulonglong2*>(smem);
    __shared__ float s_lg[TPB][E];
    __shared__ float s_cnt[E];
    __shared__ float s_psum[E];
    __shared__ unsigned int s_last;

    const int tid  = threadIdx.x;
    const int warp = tid >> 5;
    const int lane = tid & 31;
    const int hc   = lane & 15;      // h-chunk slot within iter
    const int grp  = lane >> 4;      // 0: experts 0-3, 1: experts 4-7

    if (tid < E)            s_cnt[tid] = 0.0f;
    else if (tid < 2 * E)   s_psum[tid - E] = 0.0f;

    // stage weight [E,H] into smem with padded row stride (conflict-free split)
    {
        const float4* wg = reinterpret_cast<const float4*>(w);
        float4*       ws = reinterpret_cast<float4*>(smem);
        #pragma unroll
        for (int i = 0; i < (E * HV) / NTHR; i++) {
            const int idx = tid + i * NTHR;
            const int e   = idx >> 9;          // /512
            const int c   = idx & 511;
            ws[e * WSTR + c] = wg[idx];
        }
    }
    __syncthreads();

    const int tok0 = blockIdx.x * TPB + warp * TPW;
    const ulonglong2* x8 = reinterpret_cast<const ulonglong2*>(x)
                         + (size_t)tok0 * HV + hc;
    const ulonglong2* wg8 = w8s + (size_t)(grp * 4) * WSTR + hc;

    unsigned long long acc2[TPW][4];   // [token][expert-in-group], h-packed
    #pragma unroll
    for (int t = 0; t < TPW; t++)
        #pragma unroll
        for (int k = 0; k < 4; k++)
            acc2[t][k] = 0ull;

    #pragma unroll 2
    for (int it = 0; it < NIT; it++) {
        const int c = it * 16;
        ulonglong2 xv[TPW];
        #pragma unroll
        for (int t = 0; t < TPW; t++)
            xv[t] = __ldcs(&x8[(size_t)t * HV + c]);   // halves mirror: coalesced
        #pragma unroll
        for (int k = 0; k < 4; k++) {
            const ulonglong2 wv = wg8[(size_t)k * WSTR + c];
            #pragma unroll
            for (int t = 0; t < TPW; t++) {
                ffma2(acc2[t][k], xv[t].x, wv.x);
                ffma2(acc2[t][k], xv[t].y, wv.y);
            }
        }
    }

    // reduce within each 16-lane half (xor 1,2,4,8 stays inside the half)
    float accf[TPW][4];
    #pragma unroll
    for (int t = 0; t < TPW; t++)
        #pragma unroll
        for (int k = 0; k < 4; k++) {
            float v = pair_sum(acc2[t][k]);
            v += __shfl_xor_sync(0xffffffffu, v, 8);
            v += __shfl_xor_sync(0xffffffffu, v, 4);
            v += __shfl_xor_sync(0xffffffffu, v, 2);
            v += __shfl_xor_sync(0xffffffffu, v, 1);
            accf[t][k] = v;
        }

    // lanes 0 and 16 publish their expert-group logits
    if (hc == 0) {
        #pragma unroll
        for (int t = 0; t < TPW; t++)
            #pragma unroll
            for (int k = 0; k < 4; k++)
                s_lg[warp * TPW + t][grp * 4 + k] = accf[t][k];
    }
    __syncthreads();

    // one thread per token: softmax + top-2 + outputs + block accumulators
    if (tid < TPB) {
        const int tok = blockIdx.x * TPB + tid;
        float lg[E];
        #pragma unroll
        for (int e = 0; e < E; e++) lg[e] = s_lg[tid][e];

        float m = lg[0];
        #pragma unroll
        for (int e = 1; e < E; e++) m = fmaxf(m, lg[e]);
        float p[E];
        float s = 0.0f;
        #pragma unroll
        for (int e = 0; e < E; e++) { p[e] = __expf(lg[e] - m); s += p[e]; }
        const float inv = 1.0f / s;

        int i1 = 0; float b1 = lg[0];
        #pragma unroll
        for (int e = 1; e < E; e++)
            if (lg[e] > b1) { b1 = lg[e]; i1 = e; }
        int i2 = -1; float b2 = -INFINITY;
        #pragma unroll
        for (int e = 0; e < E; e++)
            if (e != i1 && lg[e] > b2) { b2 = lg[e]; i2 = e; }

        out_idx[2 * tok]     = (float)i1;
        out_idx[2 * tok + 1] = (float)i2;
        out_wgt[2 * tok]     = p[i1] * inv;
        out_wgt[2 * tok + 1] = p[i2] * inv;

        atomicAdd(&s_cnt[i1], 1.0f);
        atomicAdd(&s_cnt[i2], 1.0f);
        #pragma unroll
        for (int e = 0; e < E; e++)
            atomicAdd(&s_psum[e], p[e] * inv);
    }

    __syncthreads();
    if (tid < E)           atomicAdd(&g_acc[tid], s_cnt[tid]);
    else if (tid < 2 * E)  atomicAdd(&g_acc[tid], s_psum[tid - E]);
    __threadfence();
    __syncthreads();

    // fused finalize: last block computes aux_loss and resets accumulators
    if (tid == 0)
        s_last = (atomicAdd(&g_done, 1u) == gridDim.x - 1) ? 1u : 0u;
    __syncthreads();

    if (s_last && tid == 0) {
        float aux = 0.0f;
        const float invT  = 1.0f / (float)T;
        const float invTK = 1.0f / ((float)T * 2.0f);
        #pragma unroll
        for (int e = 0; e < E; e++) {
            const float cnt  = atomicAdd(&g_acc[e], 0.0f);
            const float psum = atomicAdd(&g_acc[E + e], 0.0f);
            aux += (psum * invT) * (cnt * invTK * (float)E);
        }
        out_aux[0] = aux * ALPHA;
        #pragma unroll
        for (int i = 0; i < 2 * E; i++) {
            float old = atomicAdd(&g_acc[i], 0.0f);
            atomicAdd(&g_acc[i], -old);
        }
        atomicExch(&g_done, 0u);
    }
}

extern "C" void kernel_launch(void* const* d_in, const int* in_sizes, int n_in,
                              void* d_out, int out_size)
{
    const float* x = (const float*)d_in[0];   // [T, H]
    const float* w = (const float*)d_in[1];   // [E, H]
    const int T = in_sizes[0] / H;            // 16384

    float* out = (float*)d_out;
    float* out_idx = out;
    float* out_wgt = out + (size_t)T * 2;
    float* out_aux = out + (size_t)T * 4;

    const int smem_bytes = E * WSTR * 16;     // 65664 B padded weights
    cudaFuncSetAttribute(moe_gate_kernel,
                         cudaFuncAttributeMaxDynamicSharedMemorySize, smem_bytes);

    moe_gate_kernel<<<T / TPB, NTHR, smem_bytes>>>(x, w, out_idx, out_wgt, out_aux, T);
}

// round 13
// speedup vs baseline: 1.0075x; 1.0075x over previous
#include <cuda_runtime.h>
#include <math.h>

#define H       2048
#define E       8
#define HV      (H / 4)        // 512 16B-chunks per row
#define WSTR    513            // padded weight row stride in 16B units
#define TPW     8              // tokens per warp
#define NWARPS  8
#define TPB     (TPW * NWARPS) // 64 tokens per block
#define NTHR    256
#define NIT     32             // 16 h-chunks per iter
#define ALPHA   0.01f

__device__ float        g_acc[2 * E];   // [0..7] counts, [8..15] prob sums
__device__ unsigned int g_done = 0;

__device__ __forceinline__ void ffma2(unsigned long long& d,
                                      unsigned long long a,
                                      unsigned long long b)
{
    asm("fma.rn.f32x2 %0, %1, %2, %0;" : "+l"(d) : "l"(a), "l"(b));
}

__device__ __forceinline__ float pair_sum(unsigned long long p)
{
    float lo, hi;
    asm("mov.b64 {%0, %1}, %2;" : "=f"(lo), "=f"(hi) : "l"(p));
    return lo + hi;
}

__global__ __launch_bounds__(NTHR, 2)
void moe_gate_kernel(const float* __restrict__ x,
                     const float* __restrict__ w,
                     float* __restrict__ out_idx,
                     float* __restrict__ out_wgt,
                     float* __restrict__ out_aux,
                     int T)
{
    extern __shared__ char smem[];               // padded weights: 8*513*16B
    ulonglong2* w8s = reinterpret_cast<ulonglong2*>(smem);
    __shared__ float s_lg[TPB][E];
    __shared__ float s_cnt[E];
    __shared__ float s_psum[E];
    __shared__ unsigned int s_last;

    const int tid  = threadIdx.x;
    const int warp = tid >> 5;
    const int lane = tid & 31;
    const int hc   = lane & 15;      // h-chunk slot within iter
    const int grp  = lane >> 4;      // 0: experts 0-3, 1: experts 4-7

    if (tid < E)            s_cnt[tid] = 0.0f;
    else if (tid < 2 * E)   s_psum[tid - E] = 0.0f;

    // stage weight [E,H] into smem with padded row stride (conflict-free split)
    {
        const float4* wg = reinterpret_cast<const float4*>(w);
        float4*       ws = reinterpret_cast<float4*>(smem);
        #pragma unroll
        for (int i = 0; i < (E * HV) / NTHR; i++) {
            const int idx = tid + i * NTHR;
            const int e   = idx >> 9;          // /512
            const int c   = idx & 511;
            ws[e * WSTR + c] = wg[idx];
        }
    }
    __syncthreads();

    const int tok0 = blockIdx.x * TPB + warp * TPW;
    const ulonglong2* x8 = reinterpret_cast<const ulonglong2*>(x)
                         + (size_t)tok0 * HV + hc;
    const ulonglong2* wg8 = w8s + (size_t)(grp * 4) * WSTR + hc;

    unsigned long long acc2[TPW][4];   // [token][expert-in-group], h-packed
    #pragma unroll
    for (int t = 0; t < TPW; t++)
        #pragma unroll
        for (int k = 0; k < 4; k++)
            acc2[t][k] = 0ull;

    #pragma unroll 2
    for (int it = 0; it < NIT; it++) {
        const int c = it * 16;
        ulonglong2 xv[TPW];
        #pragma unroll
        for (int t = 0; t < TPW; t++)
            xv[t] = __ldcs(&x8[(size_t)t * HV + c]);   // halves mirror: coalesced
        #pragma unroll
        for (int k = 0; k < 4; k++) {
            const ulonglong2 wv = wg8[(size_t)k * WSTR + c];
            #pragma unroll
            for (int t = 0; t < TPW; t++) {
                ffma2(acc2[t][k], xv[t].x, wv.x);
                ffma2(acc2[t][k], xv[t].y, wv.y);
            }
        }
    }

    // reduce within each 16-lane half (xor 1,2,4,8 stays inside the half)
    float accf[TPW][4];
    #pragma unroll
    for (int t = 0; t < TPW; t++)
        #pragma unroll
        for (int k = 0; k < 4; k++) {
            float v = pair_sum(acc2[t][k]);
            v += __shfl_xor_sync(0xffffffffu, v, 8);
            v += __shfl_xor_sync(0xffffffffu, v, 4);
            v += __shfl_xor_sync(0xffffffffu, v, 2);
            v += __shfl_xor_sync(0xffffffffu, v, 1);
            accf[t][k] = v;
        }

    // lanes 0 and 16 publish their expert-group logits
    if (hc == 0) {
        #pragma unroll
        for (int t = 0; t < TPW; t++)
            #pragma unroll
            for (int k = 0; k < 4; k++)
                s_lg[warp * TPW + t][grp * 4 + k] = accf[t][k];
    }
    __syncthreads();

    // one thread per token: softmax + top-2 + outputs + block accumulators
    if (tid < TPB) {
        const int tok = blockIdx.x * TPB + tid;
        float lg[E];
        #pragma unroll
        for (int e = 0; e < E; e++) lg[e] = s_lg[tid][e];

        float m = lg[0];
        #pragma unroll
        for (int e = 1; e < E; e++) m = fmaxf(m, lg[e]);
        float p[E];
        float s = 0.0f;
        #pragma unroll
        for (int e = 0; e < E; e++) { p[e] = __expf(lg[e] - m); s += p[e]; }
        const float inv = 1.0f / s;

        int i1 = 0; float b1 = lg[0];
        #pragma unroll
        for (int e = 1; e < E; e++)
            if (lg[e] > b1) { b1 = lg[e]; i1 = e; }
        int i2 = -1; float b2 = -INFINITY;
        #pragma unroll
        for (int e = 0; e < E; e++)
            if (e != i1 && lg[e] > b2) { b2 = lg[e]; i2 = e; }

        out_idx[2 * tok]     = (float)i1;
        out_idx[2 * tok + 1] = (float)i2;
        out_wgt[2 * tok]     = p[i1] * inv;
        out_wgt[2 * tok + 1] = p[i2] * inv;

        atomicAdd(&s_cnt[i1], 1.0f);
        atomicAdd(&s_cnt[i2], 1.0f);
        #pragma unroll
        for (int e = 0; e < E; e++)
            atomicAdd(&s_psum[e], p[e] * inv);
    }

    __syncthreads();
    if (tid < E)           atomicAdd(&g_acc[tid], s_cnt[tid]);
    else if (tid < 2 * E)  atomicAdd(&g_acc[tid], s_psum[tid - E]);
    __threadfence();
    __syncthreads();

    // fused finalize: last block computes aux_loss and resets accumulators
    if (tid == 0)
        s_last = (atomicAdd(&g_done, 1u) == gridDim.x - 1) ? 1u : 0u;
    __syncthreads();

    if (s_last && tid == 0) {
        float aux = 0.0f;
        const float invT  = 1.0f / (float)T;
        const float invTK = 1.0f / ((float)T * 2.0f);
        #pragma unroll
        for (int e = 0; e < E; e++) {
            const float cnt  = atomicAdd(&g_acc[e], 0.0f);
            const float psum = atomicAdd(&g_acc[E + e], 0.0f);
            aux += (psum * invT) * (cnt * invTK * (float)E);
        }
        out_aux[0] = aux * ALPHA;
        #pragma unroll
        for (int i = 0; i < 2 * E; i++) {
            float old = atomicAdd(&g_acc[i], 0.0f);
            atomicAdd(&g_acc[i], -old);
        }
        atomicExch(&g_done, 0u);
    }
}

extern "C" void kernel_launch(void* const* d_in, const int* in_sizes, int n_in,
                              void* d_out, int out_size)
{
    const float* x = (const float*)d_in[0];   // [T, H]
    const float* w = (const float*)d_in[1];   // [E, H]
    const int T = in_sizes[0] / H;            // 16384

    float* out = (float*)d_out;
    float* out_idx = out;
    float* out_wgt = out + (size_t)T * 2;
    float* out_aux = out + (size_t)T * 4;

    const int smem_bytes = E * WSTR * 16;     // 65664 B padded weights
    cudaFuncSetAttribute(moe_gate_kernel,
                         cudaFuncAttributeMaxDynamicSharedMemorySize, smem_bytes);

    moe_gate_kernel<<<T / TPB, NTHR, smem_bytes>>>(x, w, out_idx, out_wgt, out_aux, T);
}

// round 14
// speedup vs baseline: 1.0102x; 1.0027x over previous
#include <cuda_runtime.h>
#include <math.h>

#define H       2048
#define E       8
#define HV      (H / 4)        // 512 16B-chunks per row
#define WSTR    513            // padded weight row stride in 16B units
#define TPW     8              // tokens per warp
#define NWARPS  8
#define TPB     (TPW * NWARPS) // 64 tokens per block
#define NTHR    256
#define NIT     32             // 16 h-chunks per iter
#define ALPHA   0.01f

__device__ float        g_acc[2 * E];   // [0..7] counts, [8..15] prob sums
__device__ unsigned int g_done = 0;

__device__ __forceinline__ void ffma2(unsigned long long& d,
                                      unsigned long long a,
                                      unsigned long long b)
{
    asm("fma.rn.f32x2 %0, %1, %2, %0;" : "+l"(d) : "l"(a), "l"(b));
}

__device__ __forceinline__ float pair_sum(unsigned long long p)
{
    float lo, hi;
    asm("mov.b64 {%0, %1}, %2;" : "=f"(lo), "=f"(hi) : "l"(p));
    return lo + hi;
}

__global__ __launch_bounds__(NTHR, 2)
void moe_gate_kernel(const float* __restrict__ x,
                     const float* __restrict__ w,
                     float* __restrict__ out_idx,
                     float* __restrict__ out_wgt,
                     float* __restrict__ out_aux,
                     int T)
{
    extern __shared__ char smem[];               // padded weights: 8*513*16B
    ulonglong2* w8s = reinterpret_cast<ulonglong2*>(smem);
    __shared__ float s_lg[TPB][E];
    __shared__ float s_cnt[E];
    __shared__ float s_psum[E];
    __shared__ unsigned int s_last;

    const int tid  = threadIdx.x;
    const int warp = tid >> 5;
    const int lane = tid & 31;
    const int hc   = lane & 15;      // h-chunk slot within iter
    const int grp  = lane >> 4;      // 0: experts 0-3, 1: experts 4-7

    if (tid < E)            s_cnt[tid] = 0.0f;
    else if (tid < 2 * E)   s_psum[tid - E] = 0.0f;

    // stage weight [E,H] into smem with padded row stride (conflict-free split)
    {
        const float4* wg = reinterpret_cast<const float4*>(w);
        float4*       ws = reinterpret_cast<float4*>(smem);
        #pragma unroll
        for (int i = 0; i < (E * HV) / NTHR; i++) {
            const int idx = tid + i * NTHR;
            const int e   = idx >> 9;          // /512
            const int c   = idx & 511;
            ws[e * WSTR + c] = wg[idx];
        }
    }
    __syncthreads();

    const int tok0 = blockIdx.x * TPB + warp * TPW;
    const ulonglong2* x8 = reinterpret_cast<const ulonglong2*>(x)
                         + (size_t)tok0 * HV + hc;
    const ulonglong2* wg8 = w8s + (size_t)(grp * 4) * WSTR + hc;

    unsigned long long acc2[TPW][4];   // [token][expert-in-group], h-packed
    #pragma unroll
    for (int t = 0; t < TPW; t++)
        #pragma unroll
        for (int k = 0; k < 4; k++)
            acc2[t][k] = 0ull;

    #pragma unroll 2
    for (int it = 0; it < NIT; it++) {
        const int c = it * 16;
        ulonglong2 xv[TPW];
        #pragma unroll
        for (int t = 0; t < TPW; t++)
            xv[t] = __ldcs(&x8[(size_t)t * HV + c]);   // halves mirror: coalesced
        #pragma unroll
        for (int k = 0; k < 4; k++) {
            const ulonglong2 wv = wg8[(size_t)k * WSTR + c];
            #pragma unroll
            for (int t = 0; t < TPW; t++) {
                ffma2(acc2[t][k], xv[t].x, wv.x);
                ffma2(acc2[t][k], xv[t].y, wv.y);
            }
        }
    }

    // reduce within each 16-lane half (xor 1,2,4,8 stays inside the half)
    float accf[TPW][4];
    #pragma unroll
    for (int t = 0; t < TPW; t++)
        #pragma unroll
        for (int k = 0; k < 4; k++) {
            float v = pair_sum(acc2[t][k]);
            v += __shfl_xor_sync(0xffffffffu, v, 8);
            v += __shfl_xor_sync(0xffffffffu, v, 4);
            v += __shfl_xor_sync(0xffffffffu, v, 2);
            v += __shfl_xor_sync(0xffffffffu, v, 1);
            accf[t][k] = v;
        }

    // lanes 0 and 16 publish their expert-group logits
    if (hc == 0) {
        #pragma unroll
        for (int t = 0; t < TPW; t++)
            #pragma unroll
            for (int k = 0; k < 4; k++)
                s_lg[warp * TPW + t][grp * 4 + k] = accf[t][k];
    }
    __syncthreads();

    // one thread per token: softmax + top-2 + outputs + block accumulators
    if (tid < TPB) {
        const int tok = blockIdx.x * TPB + tid;
        float lg[E];
        #pragma unroll
        for (int e = 0; e < E; e++) lg[e] = s_lg[tid][e];

        float m = lg[0];
        #pragma unroll
        for (int e = 1; e < E; e++) m = fmaxf(m, lg[e]);
        float p[E];
        float s = 0.0f;
        #pragma unroll
        for (int e = 0; e < E; e++) { p[e] = __expf(lg[e] - m); s += p[e]; }
        const float inv = 1.0f / s;

        int i1 = 0; float b1 = lg[0];
        #pragma unroll
        for (int e = 1; e < E; e++)
            if (lg[e] > b1) { b1 = lg[e]; i1 = e; }
        int i2 = -1; float b2 = -INFINITY;
        #pragma unroll
        for (int e = 0; e < E; e++)
            if (e != i1 && lg[e] > b2) { b2 = lg[e]; i2 = e; }

        out_idx[2 * tok]     = (float)i1;
        out_idx[2 * tok + 1] = (float)i2;
        out_wgt[2 * tok]     = p[i1] * inv;
        out_wgt[2 * tok + 1] = p[i2] * inv;

        atomicAdd(&s_cnt[i1], 1.0f);
        atomicAdd(&s_cnt[i2], 1.0f);
        #pragma unroll
        for (int e = 0; e < E; e++)
            atomicAdd(&s_psum[e], p[e] * inv);
    }

    __syncthreads();
    if (tid < E)           atomicAdd(&g_acc[tid], s_cnt[tid]);
    else if (tid < 2 * E)  atomicAdd(&g_acc[tid], s_psum[tid - E]);
    __threadfence();
    __syncthreads();

    // fused finalize: last block computes aux_loss and resets accumulators
    if (tid == 0)
        s_last = (atomicAdd(&g_done, 1u) == gridDim.x - 1) ? 1u : 0u;
    __syncthreads();

    if (s_last && tid == 0) {
        float aux = 0.0f;
        const float invT  = 1.0f / (float)T;
        const float invTK = 1.0f / ((float)T * 2.0f);
        #pragma unroll
        for (int e = 0; e < E; e++) {
            const float cnt  = atomicAdd(&g_acc[e], 0.0f);
            const float psum = atomicAdd(&g_acc[E + e], 0.0f);
            aux += (psum * invT) * (cnt * invTK * (float)E);
        }
        out_aux[0] = aux * ALPHA;
        #pragma unroll
        for (int i = 0; i < 2 * E; i++) {
            float old = atomicAdd(&g_acc[i], 0.0f);
            atomicAdd(&g_acc[i], -old);
        }
        atomicExch(&g_done, 0u);
    }
}

extern "C" void kernel_launch(void* const* d_in, const int* in_sizes, int n_in,
                              void* d_out, int out_size)
{
    const float* x = (const float*)d_in[0];   // [T, H]
    const float* w = (const float*)d_in[1];   // [E, H]
    const int T = in_sizes[0] / H;            // 16384

    float* out = (float*)d_out;
    float* out_idx = out;
    float* out_wgt = out + (size_t)T * 2;
    float* out_aux = out + (size_t)T * 4;

    const int smem_bytes = E * WSTR * 16;     // 65664 B padded weights
    cudaFuncSetAttribute(moe_gate_kernel,
                         cudaFuncAttributeMaxDynamicSharedMemorySize, smem_bytes);

    moe_gate_kernel<<<T / TPB, NTHR, smem_bytes>>>(x, w, out_idx, out_wgt, out_aux, T);
}

// round 15
// speedup vs baseline: 1.2636x; 1.2508x over previous
#include <cuda_runtime.h>
#include <math.h>

#define H       2048
#define E       8
#define HV      (H / 4)        // 512 chunks (float4) per row
#define TPW     8              // tokens per warp
#define NWARPS  8
#define TPB     (TPW * NWARPS) // 64 tokens per block
#define NTHR    256
#define NIT     (HV / 32)      // 16 main-loop iterations
#define CH_B    144            // padded bytes per chunk in pair-smem (16 u64 + pad)
#define SMEM_B  (HV * CH_B)    // 73728
#define ALPHA   0.01f

__device__ float        g_acc[2 * E];   // [0..7] counts, [8..15] prob sums
__device__ unsigned int g_done = 0;

__device__ __forceinline__ void ffma2(unsigned long long& d,
                                      unsigned long long a,
                                      unsigned long long b)
{
    asm("fma.rn.f32x2 %0, %1, %2, %0;" : "+l"(d) : "l"(a), "l"(b));
}

__device__ __forceinline__ unsigned long long dup2(float v)
{
    unsigned long long r;
    asm("mov.b64 %0, {%1, %1};" : "=l"(r) : "r"(__float_as_uint(v)));
    return r;
}

__global__ __launch_bounds__(NTHR, 2)
void moe_gate_kernel(const float* __restrict__ x,
                     const float* __restrict__ w,
                     float* __restrict__ out_idx,
                     float* __restrict__ out_wgt,
                     float* __restrict__ out_aux,
                     int T)
{
    extern __shared__ char smem[];       // pair-packed weights, 144 B per chunk
    __shared__ float s_cnt[E];
    __shared__ float s_psum[E];
    __shared__ unsigned int s_last;

    const int tid  = threadIdx.x;
    const int warp = tid >> 5;
    const int lane = tid & 31;

    if (tid < E)            s_cnt[tid] = 0.0f;
    else if (tid < 2 * E)   s_psum[tid - E] = 0.0f;

    // ---- stage pair-packed weights: chunk c holds u64 (w[2p][c*4+j], w[2p+1][c*4+j])
    // at byte offset c*144 + (j*4+p)*8. One float4 per expert row per chunk.
    {
        const float4* wg = reinterpret_cast<const float4*>(w);
        const int p = tid >> 6;          // expert pair 0..3
        const int s = tid & 63;
        #pragma unroll
        for (int q = 0; q < 8; q++) {
            const int c = q * 64 + s;    // coalesced across the 64-thread group
            const float4 a = wg[(2 * p)     * HV + c];
            const float4 b = wg[(2 * p + 1) * HV + c];
            float2* dst = reinterpret_cast<float2*>(smem + c * CH_B + p * 8);
            dst[0]  = make_float2(a.x, b.x);   // j=0
            dst[4]  = make_float2(a.y, b.y);   // j=1
            dst[8]  = make_float2(a.z, b.z);   // j=2
            dst[12] = make_float2(a.w, b.w);   // j=3
        }
    }
    __syncthreads();

    const int tok0 = blockIdx.x * TPB + warp * TPW;
    const float4* x4 = reinterpret_cast<const float4*>(x) + (size_t)tok0 * HV + lane;

    unsigned long long acc[TPW][4];      // [token][expert-pair]
    #pragma unroll
    for (int t = 0; t < TPW; t++)
        #pragma unroll
        for (int p = 0; p < 4; p++)
            acc[t][p] = 0ull;

    #pragma unroll 1
    for (int it = 0; it < NIT; it++) {
        const int c = it * 32 + lane;    // this lane's chunk (4 h values)
        // 8 independent full-width streaming LDG.128 — MLP=8, no duplication
        float4 xv[TPW];
        #pragma unroll
        for (int t = 0; t < TPW; t++)
            xv[t] = __ldcs(&x4[(size_t)t * HV + it * 32]);

        const char* wc = smem + c * CH_B;
        #pragma unroll
        for (int j = 0; j < 4; j++) {
            // 4 expert-pair u64 for this h: 2 LDS.128 (conflict-free, stride 144B)
            const ulonglong2 w01 = *reinterpret_cast<const ulonglong2*>(wc + j * 32);
            const ulonglong2 w23 = *reinterpret_cast<const ulonglong2*>(wc + j * 32 + 16);
            #pragma unroll
            for (int t = 0; t < TPW; t++) {
                const float xs = (j == 0) ? xv[t].x : (j == 1) ? xv[t].y
                               : (j == 2) ? xv[t].z : xv[t].w;
                const unsigned long long xx = dup2(xs);
                ffma2(acc[t][0], xx, w01.x);
                ffma2(acc[t][1], xx, w01.y);
                ffma2(acc[t][2], xx, w23.x);
                ffma2(acc[t][3], xx, w23.y);
            }
        }
    }

    // warp tree-reduce packed pairs (u64 shuffles)
    #pragma unroll
    for (int t = 0; t < TPW; t++)
        #pragma unroll
        for (int p = 0; p < 4; p++) {
            unsigned long long v = acc[t][p];
            float lo, hi;
            #pragma unroll
            for (int d = 16; d >= 1; d >>= 1) {
                const unsigned long long o = __shfl_xor_sync(0xffffffffu, v, d);
                asm("mov.b64 {%0, %1}, %2;" : "=f"(lo), "=f"(hi) : "l"(o));
                float l2, h2;
                asm("mov.b64 {%0, %1}, %2;" : "=f"(l2), "=f"(h2) : "l"(v));
                l2 += lo; h2 += hi;
                asm("mov.b64 %0, {%1, %2};" : "=l"(v) : "f"(l2), "f"(h2));
            }
            acc[t][p] = v;
        }

    if (lane < TPW) {
        const int tok = tok0 + lane;
        float lg[E];
        #pragma unroll
        for (int p = 0; p < 4; p++) {
            float lo, hi;
            asm("mov.b64 {%0, %1}, %2;" : "=f"(lo), "=f"(hi) : "l"(acc[lane][p]));
            lg[2 * p] = lo; lg[2 * p + 1] = hi;
        }

        float m = lg[0];
        #pragma unroll
        for (int e = 1; e < E; e++) m = fmaxf(m, lg[e]);
        float pr[E];
        float s = 0.0f;
        #pragma unroll
        for (int e = 0; e < E; e++) { pr[e] = __expf(lg[e] - m); s += pr[e]; }
        const float inv = 1.0f / s;

        int i1 = 0; float b1 = lg[0];
        #pragma unroll
        for (int e = 1; e < E; e++)
            if (lg[e] > b1) { b1 = lg[e]; i1 = e; }
        int i2 = -1; float b2 = -INFINITY;
        #pragma unroll
        for (int e = 0; e < E; e++)
            if (e != i1 && lg[e] > b2) { b2 = lg[e]; i2 = e; }

        out_idx[2 * tok]     = (float)i1;
        out_idx[2 * tok + 1] = (float)i2;
        out_wgt[2 * tok]     = pr[i1] * inv;
        out_wgt[2 * tok + 1] = pr[i2] * inv;

        atomicAdd(&s_cnt[i1], 1.0f);
        atomicAdd(&s_cnt[i2], 1.0f);
        #pragma unroll
        for (int e = 0; e < E; e++)
            atomicAdd(&s_psum[e], pr[e] * inv);
    }

    __syncthreads();
    if (tid < E)           atomicAdd(&g_acc[tid], s_cnt[tid]);
    else if (tid < 2 * E)  atomicAdd(&g_acc[tid], s_psum[tid - E]);
    __threadfence();
    __syncthreads();

    // fused finalize: last block computes aux_loss and resets accumulators
    if (tid == 0)
        s_last = (atomicAdd(&g_done, 1u) == gridDim.x - 1) ? 1u : 0u;
    __syncthreads();

    if (s_last && tid == 0) {
        float aux = 0.0f;
        const float invT  = 1.0f / (float)T;
        const float invTK = 1.0f / ((float)T * 2.0f);
        #pragma unroll
        for (int e = 0; e < E; e++) {
            const float cnt  = atomicAdd(&g_acc[e], 0.0f);
            const float psum = atomicAdd(&g_acc[E + e], 0.0f);
            aux += (psum * invT) * (cnt * invTK * (float)E);
        }
        out_aux[0] = aux * ALPHA;
        #pragma unroll
        for (int i = 0; i < 2 * E; i++) {
            float old = atomicAdd(&g_acc[i], 0.0f);
            atomicAdd(&g_acc[i], -old);
        }
        atomicExch(&g_done, 0u);
    }
}

extern "C" void kernel_launch(void* const* d_in, const int* in_sizes, int n_in,
                              void* d_out, int out_size)
{
    const float* x = (const float*)d_in[0];   // [T, H]
    const float* w = (const float*)d_in[1];   // [E, H]
    const int T = in_sizes[0] / H;            // 16384

    float* out = (float*)d_out;
    float* out_idx = out;
    float* out_wgt = out + (size_t)T * 2;
    float* out_aux = out + (size_t)T * 4;

    cudaFuncSetAttribute(moe_gate_kernel,
                         cudaFuncAttributeMaxDynamicSharedMemorySize, SMEM_B);

    moe_gate_kernel<<<T / TPB, NTHR, SMEM_B>>>(x, w, out_idx, out_wgt, out_aux, T);
}

// round 16
// speedup vs baseline: 1.3826x; 1.0942x over previous
#include <cuda_runtime.h>
#include <math.h>

#define H       2048
#define E       8
#define HV      (H / 4)        // 512 chunks (float4) per row
#define TPW     8              // tokens per warp
#define NWARPS  8
#define TPB     (TPW * NWARPS) // 64 tokens per block
#define NTHR    256
#define NIT     (HV / 32)      // 16 main-loop iterations
#define PF      3              // L2-prefetch distance in iterations
#define CH_B    144            // padded bytes per chunk in pair-smem
#define SMEM_B  (HV * CH_B)    // 73728
#define ALPHA   0.01f

__device__ float        g_acc[2 * E];   // [0..7] counts, [8..15] prob sums
__device__ unsigned int g_done = 0;

__device__ __forceinline__ void ffma2(unsigned long long& d,
                                      unsigned long long a,
                                      unsigned long long b)
{
    asm("fma.rn.f32x2 %0, %1, %2, %0;" : "+l"(d) : "l"(a), "l"(b));
}

__device__ __forceinline__ unsigned long long dup2(float v)
{
    unsigned long long r;
    asm("mov.b64 %0, {%1, %1};" : "=l"(r) : "r"(__float_as_uint(v)));
    return r;
}

__device__ __forceinline__ void pf_l2(const void* p)
{
    asm volatile("prefetch.global.L2 [%0];" :: "l"(p));
}

__global__ __launch_bounds__(NTHR, 2)
void moe_gate_kernel(const float* __restrict__ x,
                     const float* __restrict__ w,
                     float* __restrict__ out_idx,
                     float* __restrict__ out_wgt,
                     float* __restrict__ out_aux,
                     int T)
{
    extern __shared__ char smem[];       // pair-packed weights, 144 B per chunk
    __shared__ float s_cnt[E];
    __shared__ float s_psum[E];
    __shared__ unsigned int s_last;

    const int tid  = threadIdx.x;
    const int warp = tid >> 5;
    const int lane = tid & 31;

    if (tid < E)            s_cnt[tid] = 0.0f;
    else if (tid < 2 * E)   s_psum[tid - E] = 0.0f;

    const int tok0 = blockIdx.x * TPB + warp * TPW;

    // per-lane L2-prefetch pointer: lane = token*4 + quarter → one 128B line
    const char* pfp = reinterpret_cast<const char*>(
        x + (size_t)(tok0 + (lane >> 2)) * H + (lane & 3) * 32);

    // prologue: lines for iterations 0..PF-1 into L2 (fire-and-forget)
    #pragma unroll
    for (int s = 0; s < PF; s++)
        pf_l2(pfp + (size_t)s * 512);

    // ---- stage pair-packed weights: chunk c holds u64 (w[2p][c*4+j], w[2p+1][c*4+j])
    {
        const float4* wg = reinterpret_cast<const float4*>(w);
        const int p = tid >> 6;          // expert pair 0..3
        const int s = tid & 63;
        #pragma unroll
        for (int q = 0; q < 8; q++) {
            const int c = q * 64 + s;
            const float4 a = wg[(2 * p)     * HV + c];
            const float4 b = wg[(2 * p + 1) * HV + c];
            float2* dst = reinterpret_cast<float2*>(smem + c * CH_B + p * 8);
            dst[0]  = make_float2(a.x, b.x);
            dst[4]  = make_float2(a.y, b.y);
            dst[8]  = make_float2(a.z, b.z);
            dst[12] = make_float2(a.w, b.w);
        }
    }
    __syncthreads();

    const float4* x4 = reinterpret_cast<const float4*>(x) + (size_t)tok0 * HV + lane;

    unsigned long long acc[TPW][4];      // [token][expert-pair]
    #pragma unroll
    for (int t = 0; t < TPW; t++)
        #pragma unroll
        for (int p = 0; p < 4; p++)
            acc[t][p] = 0ull;

    #pragma unroll 1
    for (int it = 0; it < NIT; it++) {
        // prefetch iteration it+PF's 32 lines (one per lane)
        if (it + PF < NIT)
            pf_l2(pfp + (size_t)(it + PF) * 512);

        // 8 independent streaming LDG.128 — now L2 hits
        float4 xv[TPW];
        #pragma unroll
        for (int t = 0; t < TPW; t++)
            xv[t] = __ldcs(&x4[(size_t)t * HV + it * 32]);

        const char* wc = smem + (it * 32 + lane) * CH_B;
        #pragma unroll
        for (int j = 0; j < 4; j++) {
            const ulonglong2 w01 = *reinterpret_cast<const ulonglong2*>(wc + j * 32);
            const ulonglong2 w23 = *reinterpret_cast<const ulonglong2*>(wc + j * 32 + 16);
            #pragma unroll
            for (int t = 0; t < TPW; t++) {
                const float xs = (j == 0) ? xv[t].x : (j == 1) ? xv[t].y
                               : (j == 2) ? xv[t].z : xv[t].w;
                const unsigned long long xx = dup2(xs);
                ffma2(acc[t][0], xx, w01.x);
                ffma2(acc[t][1], xx, w01.y);
                ffma2(acc[t][2], xx, w23.x);
                ffma2(acc[t][3], xx, w23.y);
            }
        }
    }

    // warp tree-reduce packed pairs (u64 shuffles)
    #pragma unroll
    for (int t = 0; t < TPW; t++)
        #pragma unroll
        for (int p = 0; p < 4; p++) {
            unsigned long long v = acc[t][p];
            float lo, hi;
            #pragma unroll
            for (int d = 16; d >= 1; d >>= 1) {
                const unsigned long long o = __shfl_xor_sync(0xffffffffu, v, d);
                asm("mov.b64 {%0, %1}, %2;" : "=f"(lo), "=f"(hi) : "l"(o));
                float l2, h2;
                asm("mov.b64 {%0, %1}, %2;" : "=f"(l2), "=f"(h2) : "l"(v));
                l2 += lo; h2 += hi;
                asm("mov.b64 %0, {%1, %2};" : "=l"(v) : "f"(l2), "f"(h2));
            }
            acc[t][p] = v;
        }

    if (lane < TPW) {
        const int tok = tok0 + lane;
        float lg[E];
        #pragma unroll
        for (int p = 0; p < 4; p++) {
            float lo, hi;
            asm("mov.b64 {%0, %1}, %2;" : "=f"(lo), "=f"(hi) : "l"(acc[lane][p]));
            lg[2 * p] = lo; lg[2 * p + 1] = hi;
        }

        float m = lg[0];
        #pragma unroll
        for (int e = 1; e < E; e++) m = fmaxf(m, lg[e]);
        float pr[E];
        float s = 0.0f;
        #pragma unroll
        for (int e = 0; e < E; e++) { pr[e] = __expf(lg[e] - m); s += pr[e]; }
        const float inv = 1.0f / s;

        int i1 = 0; float b1 = lg[0];
        #pragma unroll
        for (int e = 1; e < E; e++)
            if (lg[e] > b1) { b1 = lg[e]; i1 = e; }
        int i2 = -1; float b2 = -INFINITY;
        #pragma unroll
        for (int e = 0; e < E; e++)
            if (e != i1 && lg[e] > b2) { b2 = lg[e]; i2 = e; }

        out_idx[2 * tok]     = (float)i1;
        out_idx[2 * tok + 1] = (float)i2;
        out_wgt[2 * tok]     = pr[i1] * inv;
        out_wgt[2 * tok + 1] = pr[i2] * inv;

        atomicAdd(&s_cnt[i1], 1.0f);
        atomicAdd(&s_cnt[i2], 1.0f);
        #pragma unroll
        for (int e = 0; e < E; e++)
            atomicAdd(&s_psum[e], pr[e] * inv);
    }

    __syncthreads();
    if (tid < E)           atomicAdd(&g_acc[tid], s_cnt[tid]);
    else if (tid < 2 * E)  atomicAdd(&g_acc[tid], s_psum[tid - E]);
    __threadfence();
    __syncthreads();

    // fused finalize: last block computes aux_loss and resets accumulators
    if (tid == 0)
        s_last = (atomicAdd(&g_done, 1u) == gridDim.x - 1) ? 1u : 0u;
    __syncthreads();

    if (s_last && tid == 0) {
        float aux = 0.0f;
        const float invT  = 1.0f / (float)T;
        const float invTK = 1.0f / ((float)T * 2.0f);
        #pragma unroll
        for (int e = 0; e < E; e++) {
            const float cnt  = atomicAdd(&g_acc[e], 0.0f);
            const float psum = atomicAdd(&g_acc[E + e], 0.0f);
            aux += (psum * invT) * (cnt * invTK * (float)E);
        }
        out_aux[0] = aux * ALPHA;
        #pragma unroll
        for (int i = 0; i < 2 * E; i++) {
            float old = atomicAdd(&g_acc[i], 0.0f);
            atomicAdd(&g_acc[i], -old);
        }
        atomicExch(&g_done, 0u);
    }
}

extern "C" void kernel_launch(void* const* d_in, const int* in_sizes, int n_in,
                              void* d_out, int out_size)
{
    const float* x = (const float*)d_in[0];   // [T, H]
    const float* w = (const float*)d_in[1];   // [E, H]
    const int T = in_sizes[0] / H;            // 16384

    float* out = (float*)d_out;
    float* out_idx = out;
    float* out_wgt = out + (size_t)T * 2;
    float* out_aux = out + (size_t)T * 4;

    cudaFuncSetAttribute(moe_gate_kernel,
                         cudaFuncAttributeMaxDynamicSharedMemorySize, SMEM_B);

    moe_gate_kernel<<<T / TPB, NTHR, SMEM_B>>>(x, w, out_idx, out_wgt, out_aux, T);
}